// round 3
// baseline (speedup 1.0000x reference)
#include <cuda_runtime.h>
#include <cstdint>

// EmbeddingDropout: out[row, :] = mask(v,:) ? weight[v,:] / 0.9 : 0, v = words[row]
// Mask reproduces jax.random.bernoulli(jax.random.key(42), 0.9, (V, D)) under the
// partitionable threefry scheme: bits(i) = fold(threefry2x32((0,42), hi=0, lo=i)),
// keep iff bits < 0xE6666600 (== uniform(bits) < 0.9f, exact).
// NOTE: words ships as int32 (JAX x64 disabled downgrades int64 -> int32).

#define TF_ROTL(x, r) __funnelshift_l((x), (x), (r))

__device__ __forceinline__ uint32_t threefry_fold(uint32_t ctr) {
    // key = (0, 42); ks = {0, 42, 0x1BD11BDA ^ 0 ^ 42 = 0x1BD11BF0}
    const uint32_t KS1 = 42u;
    const uint32_t KS2 = 0x1BD11BF0u;
    uint32_t x0 = 0u;          // counts_hi (0) + ks[0] (0)
    uint32_t x1 = ctr + KS1;   // counts_lo + ks[1]
#define TF_RND(r) { x0 += x1; x1 = TF_ROTL(x1, r) ^ x0; }
    TF_RND(13) TF_RND(15) TF_RND(26) TF_RND(6)
    x0 += KS1;  x1 += KS2 + 1u;
    TF_RND(17) TF_RND(29) TF_RND(16) TF_RND(24)
    x0 += KS2;  x1 += 0u  + 2u;
    TF_RND(13) TF_RND(15) TF_RND(26) TF_RND(6)
    x0 += 0u;   x1 += KS1 + 3u;
    TF_RND(17) TF_RND(29) TF_RND(16) TF_RND(24)
    x0 += KS1;  x1 += KS2 + 4u;
    TF_RND(13) TF_RND(15) TF_RND(26) TF_RND(6)
    x0 += KS2;  x1 += 0u  + 5u;
#undef TF_RND
    return x0 ^ x1;   // 32-bit XOR fold (partitionable random_bits)
}

__global__ void __launch_bounds__(256)
embedding_dropout_kernel(const int* __restrict__ words,
                         const float4* __restrict__ weight,
                         float4* __restrict__ out)
{
    const uint32_t KEEP_THRESH = 0xE6666600u;   // (0x733333 << 9): u < 0.9f
    int row = blockIdx.x;            // one output row per block
    int t   = threadIdx.x;           // 256 threads * 4 floats = D=1024

    uint32_t v = (uint32_t)words[row];                // vocab id (broadcast)
    uint32_t base = v * 1024u + (uint32_t)(t << 2);   // flat index into [V, D]

    float4 w = weight[(size_t)v * 256u + (uint32_t)t];

    // 4 independent threefry chains -> ILP on the serial round dependency
    uint32_t b0 = threefry_fold(base + 0u);
    uint32_t b1 = threefry_fold(base + 1u);
    uint32_t b2 = threefry_fold(base + 2u);
    uint32_t b3 = threefry_fold(base + 3u);

    float4 r;
    r.x = (b0 < KEEP_THRESH) ? (w.x / 0.9f) : 0.0f;
    r.y = (b1 < KEEP_THRESH) ? (w.y / 0.9f) : 0.0f;
    r.z = (b2 < KEEP_THRESH) ? (w.z / 0.9f) : 0.0f;
    r.w = (b3 < KEEP_THRESH) ? (w.w / 0.9f) : 0.0f;

    out[(size_t)row * 256u + (uint32_t)t] = r;
}

extern "C" void kernel_launch(void* const* d_in, const int* in_sizes, int n_in,
                              void* d_out, int out_size) {
    const int*    words  = (const int*)d_in[0];     // [B*S] int32 (x64 disabled)
    const float4* weight = (const float4*)d_in[1];  // [V, D] fp32
    float4*       out    = (float4*)d_out;          // [B*S, D] fp32

    int n_rows = in_sizes[0];                        // B*S = 16384
    embedding_dropout_kernel<<<n_rows, 256>>>(words, weight, out);
}

// round 4
// speedup vs baseline: 1.0554x; 1.0554x over previous
#include <cuda_runtime.h>
#include <cstdint>

// EmbeddingDropout: out[row, :] = mask(v,:) ? weight[v,:] * (1/0.9) : 0, v = words[row]
// Mask reproduces jax.random.bernoulli(jax.random.key(42), 0.9, (V, D)) under the
// partitionable threefry scheme: bits(i) = fold(threefry2x32((0,42), hi=0, lo=i)),
// keep iff bits < 0xE6666600 (== uniform(bits) < 0.9f, exact). Verified R3: 4.3e-8.
// words ships as int32 (JAX x64 disabled downgrades int64 -> int32).

#define TF_ROTL(x, r) __funnelshift_l((x), (x), (r))

__device__ __forceinline__ uint32_t threefry_fold(uint32_t ctr) {
    // key = (0, 42); ks = {0, 42, 0x1BD11BDA ^ 0 ^ 42 = 0x1BD11BF0}
    const uint32_t KS1 = 42u;
    const uint32_t KS2 = 0x1BD11BF0u;
    uint32_t x0 = 0u;          // counts_hi (0) + ks[0] (0)
    uint32_t x1 = ctr + KS1;   // counts_lo + ks[1]
#define TF_RND(r) { x0 += x1; x1 = TF_ROTL(x1, r) ^ x0; }
    TF_RND(13) TF_RND(15) TF_RND(26) TF_RND(6)
    x0 += KS1;  x1 += KS2 + 1u;
    TF_RND(17) TF_RND(29) TF_RND(16) TF_RND(24)
    x0 += KS2;  x1 += 0u  + 2u;
    TF_RND(13) TF_RND(15) TF_RND(26) TF_RND(6)
    x0 += 0u;   x1 += KS1 + 3u;
    TF_RND(17) TF_RND(29) TF_RND(16) TF_RND(24)
    x0 += KS1;  x1 += KS2 + 4u;
    TF_RND(13) TF_RND(15) TF_RND(26) TF_RND(6)
    x0 += KS2;  x1 += 0u  + 5u;
#undef TF_RND
    return x0 ^ x1;   // 32-bit XOR fold (partitionable random_bits)
}

__global__ void __launch_bounds__(256)
embedding_dropout_kernel(const int* __restrict__ words,
                         const float4* __restrict__ weight,
                         float4* __restrict__ out)
{
    const uint32_t KEEP_THRESH = 0xE6666600u;   // (0x733333 << 9): u < 0.9f
    const float    INV_KEEP    = 1.0f / 0.9f;   // <=1 ulp vs exact divide

    // 256 threads / block, 2 rows / block; each half-block (128 lanes) does one
    // row; each thread does 8 elements as two coalesced float4s 512 floats apart.
    int tid  = threadIdx.x;
    int row  = (blockIdx.x << 1) + (tid >> 7);
    int lane = tid & 127;                       // 0..127 within the row

    uint32_t v = (uint32_t)words[row];          // vocab id (broadcast within half-block)
    uint32_t base = v * 1024u + (uint32_t)(lane << 2);   // flat index into [V, D]

    const float4* wrow = weight + (size_t)v * 256u;
    float4 w0 = wrow[lane];                     // elems [lane*4 .. +3]
    float4 w1 = wrow[lane + 128];               // elems [lane*4+512 .. +3]

    // 8 independent threefry chains -> deep ILP on the serial round dependency
    uint32_t b[8];
#pragma unroll
    for (int k = 0; k < 4; k++) b[k]     = threefry_fold(base + (uint32_t)k);
#pragma unroll
    for (int k = 0; k < 4; k++) b[4 + k] = threefry_fold(base + 512u + (uint32_t)k);

    float4 r0, r1;
    r0.x = (b[0] < KEEP_THRESH) ? w0.x * INV_KEEP : 0.0f;
    r0.y = (b[1] < KEEP_THRESH) ? w0.y * INV_KEEP : 0.0f;
    r0.z = (b[2] < KEEP_THRESH) ? w0.z * INV_KEEP : 0.0f;
    r0.w = (b[3] < KEEP_THRESH) ? w0.w * INV_KEEP : 0.0f;
    r1.x = (b[4] < KEEP_THRESH) ? w1.x * INV_KEEP : 0.0f;
    r1.y = (b[5] < KEEP_THRESH) ? w1.y * INV_KEEP : 0.0f;
    r1.z = (b[6] < KEEP_THRESH) ? w1.z * INV_KEEP : 0.0f;
    r1.w = (b[7] < KEEP_THRESH) ? w1.w * INV_KEEP : 0.0f;

    float4* orow = out + (size_t)row * 256u;
    orow[lane]       = r0;
    orow[lane + 128] = r1;
}

extern "C" void kernel_launch(void* const* d_in, const int* in_sizes, int n_in,
                              void* d_out, int out_size) {
    const int*    words  = (const int*)d_in[0];     // [B*S] int32
    const float4* weight = (const float4*)d_in[1];  // [V, D] fp32
    float4*       out    = (float4*)d_out;          // [B*S, D] fp32

    int n_rows = in_sizes[0];                        // B*S = 16384 (even)
    embedding_dropout_kernel<<<n_rows / 2, 256>>>(words, weight, out);
}